// round 3
// baseline (speedup 1.0000x reference)
#include <cuda_runtime.h>

#define P_ 2
#define B_ 96
#define A_ 32
#define NT_ 24
#define N_ (B_*A_)             // 3072 atoms per pose
#define MD_ 4
#define MA_ 4
#define NPOLB_ 8
#define NSITES_ (P_*B_*NPOLB_) // 1536
#define SITES_PP_ (B_*NPOLB_)  // 768
#define NCHUNK_ B_             // 96 chunks of 32 atoms
#define C_LK_ 0.0897935610625833f

// ---------------- device scratch (no allocations allowed) ----------------
__device__ float4 g_A0[NSITES_];   // xp.xyz, ri
__device__ float4 g_A1[NSITES_];   // water0.xyz, 1/lambda_i
__device__ float4 g_A2[NSITES_];   // water1.xyz, C_LK*dG_i/lambda_i
__device__ int4   g_I [NSITES_];   // valid, b_i, a_i(loc), bt_i
__device__ float4 g_xyzr[P_*N_];   // atom x,y,z, r_j
__device__ float  g_vol [P_*N_];   // vol_j (0 if hydrogen)
__device__ float2 g_partial[P_*NCHUNK_];

// ---------------- small vec helpers ----------------
__device__ __forceinline__ float3 ld3(const float* b, int i) {
    return make_float3(b[3*i], b[3*i+1], b[3*i+2]);
}
__device__ __forceinline__ float3 sub3(float3 a, float3 b) {
    return make_float3(a.x-b.x, a.y-b.y, a.z-b.z);
}
__device__ __forceinline__ float3 cross3(float3 a, float3 b) {
    return make_float3(a.y*b.z - a.z*b.y, a.z*b.x - a.x*b.z, a.x*b.y - a.y*b.x);
}
__device__ __forceinline__ float3 norm3(float3 v) {
    float inv = rsqrtf(v.x*v.x + v.y*v.y + v.z*v.z + 1e-12f);
    return make_float3(v.x*inv, v.y*inv, v.z*inv);
}

// ---------------- phase 1: per-site geometry + per-atom params ----------------
__global__ void prep_kernel(
    const float* __restrict__ coords,      // (P,N,3)
    const int*   __restrict__ blockType,   // (P,B)
    const int*   __restrict__ bonds,       // (NT,A,2)
    const int*   __restrict__ ranges,      // (NT,A,2)
    const int*   __restrict__ n_donH,      // (NT,)
    const int*   __restrict__ n_acc,       // (NT,)
    const int*   __restrict__ donH,        // (NT,MD)
    const int*   __restrict__ don_hvy,     // (NT,MD)
    const int*   __restrict__ acc_inds,    // (NT,MA)
    const int*   __restrict__ hyb,         // (NT,MA)
    const int*   __restrict__ is_h,        // (NT,A)
    const float* __restrict__ par4,        // (NT,A,4)
    const float* __restrict__ wg,          // (2,) wdist, wang
    const float* __restrict__ sp2t,
    const float* __restrict__ sp3t,
    const float* __restrict__ ringt)
{
    int t = blockIdx.x * blockDim.x + threadIdx.x;

    // ---- per-atom data (P*N threads) ----
    if (t < P_*N_) {
        int p = t / N_;
        int j = t - p*N_;
        int b = j / A_;
        int a = j - b*A_;
        int bt = blockType[p*B_ + b];
        const float* c = coords + (size_t)t*3;
        const float* pr = par4 + (size_t)(bt*A_ + a)*4;
        g_xyzr[t] = make_float4(c[0], c[1], c[2], pr[0]);
        g_vol[t]  = is_h[bt*A_ + a] ? 0.0f : pr[3];
    }

    // ---- per-site data (NSITES threads) ----
    if (t < NSITES_) {
        int s  = t & (NPOLB_ - 1);
        int pb = t >> 3;
        int p  = pb / B_;
        int b  = pb - p*B_;
        int bt = blockType[p*B_ + b];
        const float* cb = coords + (size_t)(p*N_ + b*A_)*3;

        float wdist = wg[0], wang = wg[1];
        float3 w0, w1;
        int loc, valid;

        if (s < MD_) {                 // donor site
            int m  = s;
            valid  = (m < n_donH[bt]);
            int hi = don_hvy[bt*MD_ + m];
            int Hi = donH   [bt*MD_ + m];
            loc = hi;
            float3 hv = ld3(cb, hi);
            float3 Hx = ld3(cb, Hi);
            float3 dv = sub3(Hx, hv);
            float inv = rsqrtf(dv.x*dv.x + dv.y*dv.y + dv.z*dv.z + 1e-12f);
            float k = wdist * inv;
            w0 = make_float3(hv.x + k*dv.x, hv.y + k*dv.y, hv.z + k*dv.z);
            w1 = make_float3(1e6f, 1e6f, 1e6f);   // water #2 masked -> far away
        } else {                       // acceptor site
            int m  = s - MD_;
            valid  = (m < n_acc[bt]);
            int ai = acc_inds[bt*MA_ + m];
            loc = ai;
            int r0 = ranges[(bt*A_ + ai)*2];
            int b1 = bonds [(bt*A_ + r0)*2 + 1];
            int r1 = ranges[(bt*A_ + b1)*2];
            int b2 = bonds [(bt*A_ + r1)*2 + 1];
            float3 c  = ld3(cb, ai);
            float3 bx = ld3(cb, b1);
            float3 ax = ld3(cb, b2);
            float3 e1 = norm3(sub3(c, bx));
            float3 nr = norm3(cross3(sub3(bx, ax), e1));
            float3 e2 = cross3(nr, e1);
            int h = hyb[bt*MA_ + m];
            const float* tt = (h == 0) ? sp2t : (h == 1) ? sp3t : ringt;
            float st, ct;
            sincosf(wang, &st, &ct);
            float k1 = -wdist * ct;     // along e1
            float ks =  wdist * st;
            float s0c, c0c, s1c, c1c;
            sincosf(tt[0], &s0c, &c0c);
            sincosf(tt[1], &s1c, &c1c);
            w0 = make_float3(c.x + k1*e1.x + ks*c0c*e2.x + ks*s0c*nr.x,
                             c.y + k1*e1.y + ks*c0c*e2.y + ks*s0c*nr.y,
                             c.z + k1*e1.z + ks*c0c*e2.z + ks*s0c*nr.z);
            w1 = make_float3(c.x + k1*e1.x + ks*c1c*e2.x + ks*s1c*nr.x,
                             c.y + k1*e1.y + ks*c1c*e2.y + ks*s1c*nr.y,
                             c.z + k1*e1.z + ks*c1c*e2.z + ks*s1c*nr.z);
        }

        const float* pr = par4 + (size_t)(bt*A_ + loc)*4;
        float ri = pr[0], dgi = pr[1], lami = pr[2];
        float il = 1.0f / lami;
        float3 xp = ld3(cb, loc);

        g_A0[t] = make_float4(xp.x, xp.y, xp.z, ri);
        g_A1[t] = make_float4(w0.x, w0.y, w0.z, il);
        g_A2[t] = make_float4(w1.x, w1.y, w1.z, C_LK_ * dgi * il);
        g_I [t] = make_int4(valid, b, loc, bt);
    }
}

// ---------------- phase 2: site x atom pairs ----------------
__global__ __launch_bounds__(SITES_PP_, 2) void pair_kernel(
    const int*   __restrict__ minsep,   // (P,B,B)
    const int*   __restrict__ pathd,    // (NT,A,A)
    const float* __restrict__ gp)       // cutoff, ramp2, d2_low
{
    __shared__ float4 s_xyzr[A_];
    __shared__ float  s_vol [A_];
    __shared__ int    s_msep[B_];
    __shared__ float2 s_red[SITES_PP_/32];

    int p   = blockIdx.x / NCHUNK_;
    int cb  = blockIdx.x - p*NCHUNK_;
    int tid = threadIdx.x;

    if (tid < A_) {
        int gi = (p*NCHUNK_ + cb)*A_ + tid;
        s_xyzr[tid] = g_xyzr[gi];
        s_vol [tid] = g_vol [gi];
    }
    if (tid < B_) s_msep[tid] = minsep[(p*B_ + tid)*B_ + cb];
    __syncthreads();

    float cutoff   = gp[0];
    float cutoff2  = cutoff * cutoff;
    float ramp2    = gp[1];
    float inv_ramp = 1.0f / ramp2;
    float thr      = gp[2] + ramp2;    // d2_low + ramp2

    float sum0 = 0.0f, sum1 = 0.0f;

    int sid = p*SITES_PP_ + tid;
    int4 I  = g_I[sid];
    if (I.x) {
        float4 A0 = g_A0[sid];
        float4 A1 = g_A1[sid];
        float4 A2 = g_A2[sid];
        int b_i = I.y, a_i = I.z, bt_i = I.w;
        bool same = (b_i == cb);
        int sepFixed = same ? 0 : s_msep[b_i];
        const int* pdrow = pathd + (size_t)(bt_i*A_ + a_i)*A_;

        if (same || sepFixed >= 4) {
            #pragma unroll 4
            for (int j = 0; j < A_; j++) {
                float4 q = s_xyzr[j];
                float dx = A0.x - q.x, dy = A0.y - q.y, dz = A0.z - q.z;
                float d2 = fmaf(dx, dx, fmaf(dy, dy, dz*dz));
                d2 = fmaxf(d2, 0.01f);
                float v = s_vol[j];
                if (d2 < cutoff2 && v != 0.0f) {
                    if (same && pdrow[j] < 4) continue;
                    float d  = sqrtf(d2);
                    float x  = (d - (A0.w + q.w)) * A1.w;
                    float lk = A2.w * v * __expf(-x*x) * __frcp_rn(d2);
                    sum0 += lk;
                    // waters
                    float ex = A1.x - q.x, ey = A1.y - q.y, ez = A1.z - q.z;
                    float dw0 = fmaf(ex, ex, fmaf(ey, ey, ez*ez));
                    float fx = A2.x - q.x, fy = A2.y - q.y, fz = A2.z - q.z;
                    float dw1 = fmaf(fx, fx, fmaf(fy, fy, fz*fz));
                    float dwmin = fminf(dw0, dw1);
                    float wt = __saturatef((thr - dwmin) * inv_ramp);
                    float frac = wt*wt*(3.0f - 2.0f*wt);
                    sum1 = fmaf(lk, frac, sum1);
                }
            }
        }
    }

    // block reduction
    int lane = tid & 31, wid = tid >> 5;
    #pragma unroll
    for (int o = 16; o; o >>= 1) {
        sum0 += __shfl_xor_sync(0xffffffffu, sum0, o);
        sum1 += __shfl_xor_sync(0xffffffffu, sum1, o);
    }
    if (lane == 0) s_red[wid] = make_float2(sum0, sum1);
    __syncthreads();
    if (wid == 0) {
        float a = (lane < SITES_PP_/32) ? s_red[lane].x : 0.0f;
        float b = (lane < SITES_PP_/32) ? s_red[lane].y : 0.0f;
        #pragma unroll
        for (int o = 16; o; o >>= 1) {
            a += __shfl_xor_sync(0xffffffffu, a, o);
            b += __shfl_xor_sync(0xffffffffu, b, o);
        }
        if (lane == 0) g_partial[blockIdx.x] = make_float2(a, b);
    }
}

// ---------------- phase 3: deterministic final reduction ----------------
__global__ void finish_kernel(float* __restrict__ out)
{
    int t = threadIdx.x;
    if (t < 2*P_) {
        int comp = t / P_;
        int p    = t - comp*P_;
        const float2* base = g_partial + p*NCHUNK_;
        float s = 0.0f;
        for (int i = 0; i < NCHUNK_; i++)
            s += comp ? base[i].y : base[i].x;
        out[t] = s;   // layout (2, P) row-major
    }
}

// ---------------- launch ----------------
extern "C" void kernel_launch(void* const* d_in, const int* in_sizes, int n_in,
                              void* d_out, int out_size)
{
    const float* coords    = (const float*)d_in[0];
    const int*   blockType = (const int*)  d_in[1];
    const int*   minsep    = (const int*)  d_in[2];
    // d_in[3] = bt_n_atoms (unused: always A)
    const int*   bonds     = (const int*)  d_in[4];
    const int*   ranges    = (const int*)  d_in[5];
    const int*   n_donH    = (const int*)  d_in[6];
    const int*   n_acc     = (const int*)  d_in[7];
    const int*   donH      = (const int*)  d_in[8];
    const int*   don_hvy   = (const int*)  d_in[9];
    const int*   acc_inds  = (const int*)  d_in[10];
    const int*   hyb       = (const int*)  d_in[11];
    const int*   is_h      = (const int*)  d_in[12];
    const float* par4      = (const float*)d_in[13];
    const int*   pathd     = (const int*)  d_in[14];
    const float* gp        = (const float*)d_in[15];
    const float* wg        = (const float*)d_in[16];
    const float* sp2t      = (const float*)d_in[17];
    const float* sp3t      = (const float*)d_in[18];
    const float* ringt     = (const float*)d_in[19];

    prep_kernel<<<(P_*N_ + 255)/256, 256>>>(
        coords, blockType, bonds, ranges, n_donH, n_acc,
        donH, don_hvy, acc_inds, hyb, is_h, par4, wg, sp2t, sp3t, ringt);

    pair_kernel<<<P_*NCHUNK_, SITES_PP_>>>(minsep, pathd, gp);

    finish_kernel<<<1, 32>>>((float*)d_out);
}

// round 4
// speedup vs baseline: 1.3819x; 1.3819x over previous
#include <cuda_runtime.h>

#define P_ 2
#define B_ 96
#define A_ 32
#define NT_ 24
#define N_ (B_*A_)             // 3072 atoms per pose
#define MD_ 4
#define MA_ 4
#define NPOLB_ 8
#define SITES_PP_ (B_*NPOLB_)  // 768 sites per pose
#define CPB_ 2                 // atom chunks per block
#define BPP_ (B_/CPB_)         // 48 blocks per pose
#define NBLK_ (P_*BPP_)        // 96 blocks total
#define C_LK_ 0.0897935610625833f

// ---------------- device scratch (no allocations allowed) ----------------
__device__ float2 g_partial[NBLK_];
__device__ int    g_count = 0;

// ---------------- small vec helpers ----------------
__device__ __forceinline__ float3 ld3(const float* b, int i) {
    return make_float3(b[3*i], b[3*i+1], b[3*i+2]);
}
__device__ __forceinline__ float3 sub3(float3 a, float3 b) {
    return make_float3(a.x-b.x, a.y-b.y, a.z-b.z);
}
__device__ __forceinline__ float3 cross3(float3 a, float3 b) {
    return make_float3(a.y*b.z - a.z*b.y, a.z*b.x - a.x*b.z, a.x*b.y - a.y*b.x);
}
__device__ __forceinline__ float3 norm3(float3 v) {
    float inv = rsqrtf(v.x*v.x + v.y*v.y + v.z*v.z + 1e-12f);
    return make_float3(v.x*inv, v.y*inv, v.z*inv);
}

// ---------------- single fused kernel ----------------
__global__ __launch_bounds__(SITES_PP_, 1) void fused_kernel(
    const float* __restrict__ coords,      // (P,N,3)
    const int*   __restrict__ blockType,   // (P,B)
    const int*   __restrict__ minsep,      // (P,B,B)
    const int*   __restrict__ bonds,       // (NT,A,2)
    const int*   __restrict__ ranges,      // (NT,A,2)
    const int*   __restrict__ n_donH,      // (NT,)
    const int*   __restrict__ n_acc,       // (NT,)
    const int*   __restrict__ donH,        // (NT,MD)
    const int*   __restrict__ don_hvy,     // (NT,MD)
    const int*   __restrict__ acc_inds,    // (NT,MA)
    const int*   __restrict__ hyb,         // (NT,MA)
    const int*   __restrict__ is_h,        // (NT,A)
    const float* __restrict__ par4,        // (NT,A,4)
    const int*   __restrict__ pathd,       // (NT,A,A)
    const float* __restrict__ gp,          // cutoff, ramp2, d2_low
    const float* __restrict__ wg,          // wdist, wang
    const float* __restrict__ sp2t,
    const float* __restrict__ sp3t,
    const float* __restrict__ ringt,
    float* __restrict__ out)
{
    __shared__ float4 s_xyzr[CPB_*A_];
    __shared__ float  s_vol [CPB_*A_];
    __shared__ int    s_msep[CPB_][B_];
    __shared__ float2 s_red[SITES_PP_/32];
    __shared__ int    s_last;

    int bid = blockIdx.x;
    int p   = bid / BPP_;
    int cp  = bid - p*BPP_;
    int cb0 = cp * CPB_;
    int tid = threadIdx.x;

    // ---- chunk atom data into smem (64 threads) ----
    if (tid < CPB_*A_) {
        int chunk = tid >> 5;
        int a     = tid & 31;
        int blk   = cb0 + chunk;
        int bt    = blockType[p*B_ + blk];
        int gi    = p*N_ + blk*A_ + a;
        const float* c  = coords + (size_t)gi*3;
        const float* pr = par4 + (size_t)(bt*A_ + a)*4;
        s_xyzr[tid] = make_float4(c[0], c[1], c[2], pr[0]);
        s_vol [tid] = is_h[bt*A_ + a] ? 0.0f : pr[3];
    }
    // ---- min-bond-sep columns for the two chunks (192 threads) ----
    if (tid < CPB_*B_) {
        int ch = tid / B_;
        int b  = tid - ch*B_;
        s_msep[ch][b] = minsep[(p*B_ + b)*B_ + (cb0 + ch)];
    }

    // ---- per-thread site geometry (computed in registers) ----
    int s  = tid & (NPOLB_ - 1);
    int b_i = tid >> 3;                       // site's pose-block
    int bt_i = blockType[p*B_ + b_i];
    const float* cbase = coords + (size_t)(p*N_ + b_i*A_)*3;

    float wdist = wg[0], wang = wg[1];
    float3 w0, w1;
    int loc, valid;

    if (s < MD_) {                 // donor site
        int m  = s;
        valid  = (m < n_donH[bt_i]);
        int hi = don_hvy[bt_i*MD_ + m];
        int Hi = donH   [bt_i*MD_ + m];
        loc = hi;
        float3 hv = ld3(cbase, hi);
        float3 Hx = ld3(cbase, Hi);
        float3 dv = sub3(Hx, hv);
        float inv = rsqrtf(dv.x*dv.x + dv.y*dv.y + dv.z*dv.z + 1e-12f);
        float k = wdist * inv;
        w0 = make_float3(hv.x + k*dv.x, hv.y + k*dv.y, hv.z + k*dv.z);
        w1 = make_float3(1e6f, 1e6f, 1e6f);   // masked water #2 -> far away
    } else {                       // acceptor site
        int m  = s - MD_;
        valid  = (m < n_acc[bt_i]);
        int ai = acc_inds[bt_i*MA_ + m];
        loc = ai;
        int r0 = ranges[(bt_i*A_ + ai)*2];
        int b1 = bonds [(bt_i*A_ + r0)*2 + 1];
        int r1 = ranges[(bt_i*A_ + b1)*2];
        int b2 = bonds [(bt_i*A_ + r1)*2 + 1];
        float3 c  = ld3(cbase, ai);
        float3 bx = ld3(cbase, b1);
        float3 ax = ld3(cbase, b2);
        float3 e1 = norm3(sub3(c, bx));
        float3 nr = norm3(cross3(sub3(bx, ax), e1));
        float3 e2 = cross3(nr, e1);
        int h = hyb[bt_i*MA_ + m];
        const float* tt = (h == 0) ? sp2t : (h == 1) ? sp3t : ringt;
        float st, ct;
        sincosf(wang, &st, &ct);
        float k1 = -wdist * ct;
        float ks =  wdist * st;
        float s0c, c0c, s1c, c1c;
        sincosf(tt[0], &s0c, &c0c);
        sincosf(tt[1], &s1c, &c1c);
        w0 = make_float3(c.x + k1*e1.x + ks*c0c*e2.x + ks*s0c*nr.x,
                         c.y + k1*e1.y + ks*c0c*e2.y + ks*s0c*nr.y,
                         c.z + k1*e1.z + ks*c0c*e2.z + ks*s0c*nr.z);
        w1 = make_float3(c.x + k1*e1.x + ks*c1c*e2.x + ks*s1c*nr.x,
                         c.y + k1*e1.y + ks*c1c*e2.y + ks*s1c*nr.y,
                         c.z + k1*e1.z + ks*c1c*e2.z + ks*s1c*nr.z);
    }

    const float* prm = par4 + (size_t)(bt_i*A_ + loc)*4;
    float ri  = prm[0];
    float il  = 1.0f / prm[2];
    float cdg = C_LK_ * prm[1] * il;
    float3 xp = ld3(cbase, loc);
    const int* pdrow = pathd + (size_t)(bt_i*A_ + loc)*A_;

    __syncthreads();

    // ---- pair loop: this thread's site vs the block's 2 atom chunks ----
    float cutoff2  = gp[0]*gp[0];
    float inv_ramp = 1.0f / gp[1];
    float thr      = gp[2] + gp[1];    // d2_low + ramp2

    float sum0 = 0.0f, sum1 = 0.0f;

    if (valid) {
        #pragma unroll
        for (int ch = 0; ch < CPB_; ch++) {
            int cb = cb0 + ch;
            bool same = (b_i == cb);
            int sepF = same ? 6 : s_msep[ch][b_i];
            if (sepF >= 4) {
                const float4* qs = s_xyzr + ch*A_;
                const float*  vs = s_vol  + ch*A_;
                #pragma unroll 4
                for (int j = 0; j < A_; j++) {
                    float4 q = qs[j];
                    float dx = xp.x - q.x, dy = xp.y - q.y, dz = xp.z - q.z;
                    float d2 = fmaf(dx, dx, fmaf(dy, dy, dz*dz));
                    d2 = fmaxf(d2, 0.01f);
                    float v = vs[j];
                    if (d2 < cutoff2 && v != 0.0f) {
                        if (same && pdrow[j] < 4) continue;
                        float irt = rsqrtf(d2);
                        float d   = d2 * irt;          // sqrt(d2)
                        float x   = (d - (ri + q.w)) * il;
                        float lk  = cdg * v * __expf(-x*x) * (irt*irt);
                        sum0 += lk;
                        float ex = w0.x - q.x, ey = w0.y - q.y, ez = w0.z - q.z;
                        float dw0 = fmaf(ex, ex, fmaf(ey, ey, ez*ez));
                        float fx = w1.x - q.x, fy = w1.y - q.y, fz = w1.z - q.z;
                        float dw1 = fmaf(fx, fx, fmaf(fy, fy, fz*fz));
                        float dwmin = fminf(dw0, dw1);
                        float wt = __saturatef((thr - dwmin) * inv_ramp);
                        float frac = wt*wt*(3.0f - 2.0f*wt);
                        sum1 = fmaf(lk, frac, sum1);
                    }
                }
            }
        }
    }

    // ---- block reduction ----
    int lane = tid & 31, wid = tid >> 5;
    #pragma unroll
    for (int o = 16; o; o >>= 1) {
        sum0 += __shfl_xor_sync(0xffffffffu, sum0, o);
        sum1 += __shfl_xor_sync(0xffffffffu, sum1, o);
    }
    if (lane == 0) s_red[wid] = make_float2(sum0, sum1);
    __syncthreads();
    if (wid == 0) {
        float a = (lane < SITES_PP_/32) ? s_red[lane].x : 0.0f;
        float b = (lane < SITES_PP_/32) ? s_red[lane].y : 0.0f;
        #pragma unroll
        for (int o = 16; o; o >>= 1) {
            a += __shfl_xor_sync(0xffffffffu, a, o);
            b += __shfl_xor_sync(0xffffffffu, b, o);
        }
        if (lane == 0) {
            g_partial[bid] = make_float2(a, b);
            __threadfence();
            int t = atomicAdd(&g_count, 1);
            s_last = (t == (int)gridDim.x - 1);
        }
    }
    __syncthreads();

    // ---- last block: deterministic serial final reduction ----
    if (s_last) {
        __threadfence();
        if (tid < 2*P_) {
            int comp = tid / P_;
            int pp   = tid - comp*P_;
            const float2* base = g_partial + pp*BPP_;
            float acc = 0.0f;
            for (int i = 0; i < BPP_; i++)
                acc += comp ? base[i].y : base[i].x;
            out[tid] = acc;              // layout (2, P) row-major
        }
        if (tid == 0) g_count = 0;       // reset for next graph replay
    }
}

// ---------------- launch ----------------
extern "C" void kernel_launch(void* const* d_in, const int* in_sizes, int n_in,
                              void* d_out, int out_size)
{
    const float* coords    = (const float*)d_in[0];
    const int*   blockType = (const int*)  d_in[1];
    const int*   minsep    = (const int*)  d_in[2];
    // d_in[3] = bt_n_atoms (unused: always A)
    const int*   bonds     = (const int*)  d_in[4];
    const int*   ranges    = (const int*)  d_in[5];
    const int*   n_donH    = (const int*)  d_in[6];
    const int*   n_acc     = (const int*)  d_in[7];
    const int*   donH      = (const int*)  d_in[8];
    const int*   don_hvy   = (const int*)  d_in[9];
    const int*   acc_inds  = (const int*)  d_in[10];
    const int*   hyb       = (const int*)  d_in[11];
    const int*   is_h      = (const int*)  d_in[12];
    const float* par4      = (const float*)d_in[13];
    const int*   pathd     = (const int*)  d_in[14];
    const float* gp        = (const float*)d_in[15];
    const float* wg        = (const float*)d_in[16];
    const float* sp2t      = (const float*)d_in[17];
    const float* sp3t      = (const float*)d_in[18];
    const float* ringt     = (const float*)d_in[19];

    fused_kernel<<<NBLK_, SITES_PP_>>>(
        coords, blockType, minsep, bonds, ranges, n_donH, n_acc,
        donH, don_hvy, acc_inds, hyb, is_h, par4, pathd,
        gp, wg, sp2t, sp3t, ringt, (float*)d_out);
}

// round 5
// speedup vs baseline: 1.8804x; 1.3607x over previous
#include <cuda_runtime.h>

#define P_ 2
#define B_ 96
#define A_ 32
#define NT_ 24
#define N_ (B_*A_)             // 3072 atoms per pose
#define MD_ 4
#define MA_ 4
#define NPOLB_ 8
#define NSITES_ (P_*B_*NPOLB_) // 1536
#define SITES_PP_ (B_*NPOLB_)  // 768
#define SPB_ 256               // sites per pair-block
#define SGRP_ (SITES_PP_/SPB_) // 3 site-groups per pose
#define NBLK_ (P_*SGRP_*B_)    // 576 pair blocks
#define C_LK_ 0.0897935610625833f

// ---------------- device scratch (no allocations allowed) ----------------
__device__ float4 g_A0[NSITES_];   // xp.xyz, ri
__device__ float4 g_A1[NSITES_];   // water0.xyz, 1/lambda_i
__device__ float4 g_A2[NSITES_];   // water1.xyz, C_LK*dG_i/lambda_i
__device__ int4   g_I [NSITES_];   // valid, b_i, a_i(loc), bt_i
__device__ float4 g_xyzr[P_*N_];   // atom x,y,z, r_j
__device__ float  g_vol [P_*N_];   // vol_j (0 if hydrogen)

// ---------------- small vec helpers ----------------
__device__ __forceinline__ float3 ld3(const float* b, int i) {
    return make_float3(b[3*i], b[3*i+1], b[3*i+2]);
}
__device__ __forceinline__ float3 sub3(float3 a, float3 b) {
    return make_float3(a.x-b.x, a.y-b.y, a.z-b.z);
}
__device__ __forceinline__ float3 cross3(float3 a, float3 b) {
    return make_float3(a.y*b.z - a.z*b.y, a.z*b.x - a.x*b.z, a.x*b.y - a.y*b.x);
}
__device__ __forceinline__ float3 norm3(float3 v) {
    float inv = rsqrtf(v.x*v.x + v.y*v.y + v.z*v.z + 1e-12f);
    return make_float3(v.x*inv, v.y*inv, v.z*inv);
}

// ---------------- phase 1: per-site geometry + per-atom params + out=0 ----
__global__ void prep_kernel(
    const float* __restrict__ coords,      // (P,N,3)
    const int*   __restrict__ blockType,   // (P,B)
    const int*   __restrict__ bonds,       // (NT,A,2)
    const int*   __restrict__ ranges,      // (NT,A,2)
    const int*   __restrict__ n_donH,      // (NT,)
    const int*   __restrict__ n_acc,       // (NT,)
    const int*   __restrict__ donH,        // (NT,MD)
    const int*   __restrict__ don_hvy,     // (NT,MD)
    const int*   __restrict__ acc_inds,    // (NT,MA)
    const int*   __restrict__ hyb,         // (NT,MA)
    const int*   __restrict__ is_h,        // (NT,A)
    const float* __restrict__ par4,        // (NT,A,4)
    const float* __restrict__ wg,          // wdist, wang
    const float* __restrict__ sp2t,
    const float* __restrict__ sp3t,
    const float* __restrict__ ringt,
    float* __restrict__ out)
{
    int t = blockIdx.x * blockDim.x + threadIdx.x;

    if (t < 2*P_) out[t] = 0.0f;           // zero accumulators every call

    // ---- per-atom data ----
    if (t < P_*N_) {
        int p = t / N_;
        int j = t - p*N_;
        int b = j / A_;
        int a = j - b*A_;
        int bt = blockType[p*B_ + b];
        const float* c  = coords + (size_t)t*3;
        const float* pr = par4 + (size_t)(bt*A_ + a)*4;
        g_xyzr[t] = make_float4(c[0], c[1], c[2], pr[0]);
        g_vol[t]  = is_h[bt*A_ + a] ? 0.0f : pr[3];
    }

    // ---- per-site data ----
    if (t < NSITES_) {
        int s  = t & (NPOLB_ - 1);
        int pb = t >> 3;
        int p  = pb / B_;
        int b  = pb - p*B_;
        int bt = blockType[p*B_ + b];
        const float* cb = coords + (size_t)(p*N_ + b*A_)*3;

        float wdist = wg[0], wang = wg[1];
        float3 w0, w1;
        int loc, valid;

        if (s < MD_) {                 // donor site
            int m  = s;
            valid  = (m < n_donH[bt]);
            int hi = don_hvy[bt*MD_ + m];
            int Hi = donH   [bt*MD_ + m];
            loc = hi;
            float3 hv = ld3(cb, hi);
            float3 Hx = ld3(cb, Hi);
            float3 dv = sub3(Hx, hv);
            float inv = rsqrtf(dv.x*dv.x + dv.y*dv.y + dv.z*dv.z + 1e-12f);
            float k = wdist * inv;
            w0 = make_float3(hv.x + k*dv.x, hv.y + k*dv.y, hv.z + k*dv.z);
            w1 = make_float3(1e6f, 1e6f, 1e6f);   // masked water #2 -> far away
        } else {                       // acceptor site
            int m  = s - MD_;
            valid  = (m < n_acc[bt]);
            int ai = acc_inds[bt*MA_ + m];
            loc = ai;
            int r0 = ranges[(bt*A_ + ai)*2];
            int b1 = bonds [(bt*A_ + r0)*2 + 1];
            int r1 = ranges[(bt*A_ + b1)*2];
            int b2 = bonds [(bt*A_ + r1)*2 + 1];
            float3 c  = ld3(cb, ai);
            float3 bx = ld3(cb, b1);
            float3 ax = ld3(cb, b2);
            float3 e1 = norm3(sub3(c, bx));
            float3 nr = norm3(cross3(sub3(bx, ax), e1));
            float3 e2 = cross3(nr, e1);
            int h = hyb[bt*MA_ + m];
            const float* tt = (h == 0) ? sp2t : (h == 1) ? sp3t : ringt;
            float st, ct;
            sincosf(wang, &st, &ct);
            float k1 = -wdist * ct;
            float ks =  wdist * st;
            float s0c, c0c, s1c, c1c;
            sincosf(tt[0], &s0c, &c0c);
            sincosf(tt[1], &s1c, &c1c);
            w0 = make_float3(c.x + k1*e1.x + ks*c0c*e2.x + ks*s0c*nr.x,
                             c.y + k1*e1.y + ks*c0c*e2.y + ks*s0c*nr.y,
                             c.z + k1*e1.z + ks*c0c*e2.z + ks*s0c*nr.z);
            w1 = make_float3(c.x + k1*e1.x + ks*c1c*e2.x + ks*s1c*nr.x,
                             c.y + k1*e1.y + ks*c1c*e2.y + ks*s1c*nr.y,
                             c.z + k1*e1.z + ks*c1c*e2.z + ks*s1c*nr.z);
        }

        const float* pr = par4 + (size_t)(bt*A_ + loc)*4;
        float ri = pr[0], dgi = pr[1], lami = pr[2];
        float il = 1.0f / lami;
        float3 xp = ld3(cb, loc);

        g_A0[t] = make_float4(xp.x, xp.y, xp.z, ri);
        g_A1[t] = make_float4(w0.x, w0.y, w0.z, il);
        g_A2[t] = make_float4(w1.x, w1.y, w1.z, C_LK_ * dgi * il);
        g_I [t] = make_int4(valid, b, loc, bt);
    }
}

// ---------------- phase 2: 256 sites x one 32-atom chunk per block ----------
__global__ __launch_bounds__(SPB_) void pair_kernel(
    const int*   __restrict__ minsep,   // (P,B,B)
    const int*   __restrict__ pathd,    // (NT,A,A)
    const float* __restrict__ gp,       // cutoff, ramp2, d2_low
    float* __restrict__ out)
{
    __shared__ float4 s_xyzr[A_];
    __shared__ float  s_vol [A_];
    __shared__ float2 s_red[SPB_/32];

    int bid  = blockIdx.x;
    int cb   = bid % B_;                 // atom chunk (pose-block)
    int rest = bid / B_;
    int sg   = rest % SGRP_;             // site group
    int p    = rest / SGRP_;             // pose
    int tid  = threadIdx.x;

    if (tid < A_) {
        int gi = p*N_ + cb*A_ + tid;
        s_xyzr[tid] = g_xyzr[gi];
        s_vol [tid] = g_vol [gi];
    }

    int sid = p*SITES_PP_ + sg*SPB_ + tid;
    int4 I  = g_I[sid];
    int b_i = I.y;
    bool same = (b_i == cb);
    int sepF = same ? 6 : __ldg(&minsep[(p*B_ + b_i)*B_ + cb]);

    __syncthreads();

    float cutoff2  = gp[0]*gp[0];
    float inv_ramp = 1.0f / gp[1];
    float thr      = gp[2] + gp[1];      // d2_low + ramp2

    float sum0 = 0.0f, sum1 = 0.0f;

    if (I.x && sepF >= 4) {
        float4 A0 = g_A0[sid];
        float4 A1 = g_A1[sid];
        float4 A2 = g_A2[sid];
        const int* pdrow = pathd + (size_t)(I.w*A_ + I.z)*A_;

        #pragma unroll 8
        for (int j = 0; j < A_; j++) {
            float4 q = s_xyzr[j];
            float dx = A0.x - q.x, dy = A0.y - q.y, dz = A0.z - q.z;
            float d2 = fmaf(dx, dx, fmaf(dy, dy, dz*dz));
            d2 = fmaxf(d2, 0.01f);
            float v = s_vol[j];
            if (d2 < cutoff2 && v != 0.0f) {
                if (same && pdrow[j] < 4) continue;
                float irt = rsqrtf(d2);
                float d   = d2 * irt;            // sqrt(d2)
                float x   = (d - (A0.w + q.w)) * A1.w;
                float lk  = A2.w * v * __expf(-x*x) * (irt*irt);
                sum0 += lk;
                float ex = A1.x - q.x, ey = A1.y - q.y, ez = A1.z - q.z;
                float dw0 = fmaf(ex, ex, fmaf(ey, ey, ez*ez));
                float fx = A2.x - q.x, fy = A2.y - q.y, fz = A2.z - q.z;
                float dw1 = fmaf(fx, fx, fmaf(fy, fy, fz*fz));
                float dwmin = fminf(dw0, dw1);
                float wt = __saturatef((thr - dwmin) * inv_ramp);
                float frac = wt*wt*(3.0f - 2.0f*wt);
                sum1 = fmaf(lk, frac, sum1);
            }
        }
    }

    // ---- block reduction -> 2 atomics ----
    int lane = tid & 31, wid = tid >> 5;
    #pragma unroll
    for (int o = 16; o; o >>= 1) {
        sum0 += __shfl_xor_sync(0xffffffffu, sum0, o);
        sum1 += __shfl_xor_sync(0xffffffffu, sum1, o);
    }
    if (lane == 0) s_red[wid] = make_float2(sum0, sum1);
    __syncthreads();
    if (wid == 0) {
        float a = (lane < SPB_/32) ? s_red[lane].x : 0.0f;
        float b = (lane < SPB_/32) ? s_red[lane].y : 0.0f;
        #pragma unroll
        for (int o = 4; o; o >>= 1) {
            a += __shfl_xor_sync(0xffffffffu, a, o);
            b += __shfl_xor_sync(0xffffffffu, b, o);
        }
        if (lane == 0) {
            atomicAdd(&out[p],      a);   // component 0, pose p
            atomicAdd(&out[P_ + p], b);   // component 1, pose p
        }
    }
}

// ---------------- launch ----------------
extern "C" void kernel_launch(void* const* d_in, const int* in_sizes, int n_in,
                              void* d_out, int out_size)
{
    const float* coords    = (const float*)d_in[0];
    const int*   blockType = (const int*)  d_in[1];
    const int*   minsep    = (const int*)  d_in[2];
    // d_in[3] = bt_n_atoms (unused: always A)
    const int*   bonds     = (const int*)  d_in[4];
    const int*   ranges    = (const int*)  d_in[5];
    const int*   n_donH    = (const int*)  d_in[6];
    const int*   n_acc     = (const int*)  d_in[7];
    const int*   donH      = (const int*)  d_in[8];
    const int*   don_hvy   = (const int*)  d_in[9];
    const int*   acc_inds  = (const int*)  d_in[10];
    const int*   hyb       = (const int*)  d_in[11];
    const int*   is_h      = (const int*)  d_in[12];
    const float* par4      = (const float*)d_in[13];
    const int*   pathd     = (const int*)  d_in[14];
    const float* gp        = (const float*)d_in[15];
    const float* wg        = (const float*)d_in[16];
    const float* sp2t      = (const float*)d_in[17];
    const float* sp3t      = (const float*)d_in[18];
    const float* ringt     = (const float*)d_in[19];

    prep_kernel<<<(P_*N_ + 127)/128, 128>>>(
        coords, blockType, bonds, ranges, n_donH, n_acc,
        donH, don_hvy, acc_inds, hyb, is_h, par4,
        wg, sp2t, sp3t, ringt, (float*)d_out);

    pair_kernel<<<NBLK_, SPB_>>>(minsep, pathd, gp, (float*)d_out);
}